// round 7
// baseline (speedup 1.0000x reference)
#include <cuda_runtime.h>
#include <cuda_bf16.h>
#include <cstdint>

// CausalTrajectoryPrediction: fused 3-GEMM MLP, mma.sync m16n8k16 bf16,
// register-chained. R7: branch-split warp pairing — warps w and w^4 share the
// same 32 batch rows; w handles branch-0 (L1+L2), w^4 branch-1, halving the
// per-row B-fragment smem traffic (the measured bottleneck). L3 split n-wise
// across the pair; A3 halves exchanged via one STS.128/LDS.128 each; final
// layer-4 partials combined through a 128-float smem buffer.

namespace {
constexpr int kB       = 16384;
constexpr int kBT      = 128;
constexpr int kThreads = 256;
constexpr int kXS      = 72;     // X row stride in bf16 elems (144 B)

constexpr uint32_t OFF_X   = 0;          // bf16 [128][72] = 18432
constexpr uint32_t OFF_BP1 = 18432;      // uint2 [2sp][128][8] = 16384
constexpr uint32_t OFF_BP2 = 34816;      // uint2 [2br][2sp][32][8] = 8192
constexpr uint32_t OFF_BP3 = 43008;      // uint2 [2sp][64][8] = 8192
constexpr uint32_t OFF_EX  = 51200;      // uint4 [8wid][4][32] = 16384
constexpr uint32_t OFF_PS  = 67584;      // float [128]
constexpr uint32_t OFF_XI  = 68096;      // float [128]
constexpr uint32_t OFF_W3X = 68608;      // float [64]
constexpr uint32_t OFF_B3A = 68864;      // float [64]
constexpr uint32_t OFF_W3B = 69120;      // float [64]
constexpr uint32_t OFF_B3B = 69376;      // float
constexpr uint32_t SMEM_BYTES = 69392;
} // namespace

__device__ __forceinline__ uint32_t smem_u32(const void* p) {
    uint32_t a;
    asm("{ .reg .u64 t; cvta.to.shared.u64 t, %1; cvt.u32.u64 %0, t; }"
        : "=r"(a) : "l"(p));
    return a;
}
__device__ __forceinline__ uint32_t bf2(float a, float b) {
    __nv_bfloat162 h = __floats2bfloat162_rn(a, b);
    return *reinterpret_cast<uint32_t*>(&h);
}
__device__ __forceinline__ void ldmat4(uint32_t r[4], uint32_t saddr) {
    asm volatile("ldmatrix.sync.aligned.m8n8.x4.shared.b16 {%0,%1,%2,%3}, [%4];"
                 : "=r"(r[0]), "=r"(r[1]), "=r"(r[2]), "=r"(r[3]) : "r"(saddr));
}
__device__ __forceinline__ void mma16(float d[4], const uint32_t a[4],
                                      uint32_t b0, uint32_t b1) {
    asm volatile(
        "mma.sync.aligned.m16n8k16.row.col.f32.bf16.bf16.f32 "
        "{%0,%1,%2,%3}, {%4,%5,%6,%7}, {%8,%9}, {%0,%1,%2,%3};"
        : "+f"(d[0]), "+f"(d[1]), "+f"(d[2]), "+f"(d[3])
        : "r"(a[0]), "r"(a[1]), "r"(a[2]), "r"(a[3]), "r"(b0), "r"(b1));
}
__device__ __forceinline__ void pack2(uint32_t a[4], const float c0[4],
                                      const float c1[4]) {
    a[0] = bf2(fmaxf(c0[0], 0.f), fmaxf(c0[1], 0.f));
    a[1] = bf2(fmaxf(c0[2], 0.f), fmaxf(c0[3], 0.f));
    a[2] = bf2(fmaxf(c1[0], 0.f), fmaxf(c1[1], 0.f));
    a[3] = bf2(fmaxf(c1[2], 0.f), fmaxf(c1[3], 0.f));
}

__global__ void __launch_bounds__(kThreads, 2)
ctp_r7_kernel(const float* __restrict__ x,
              const float* __restrict__ W1a, const float* __restrict__ W1b,
              const float* __restrict__ W2a, const float* __restrict__ W2b,
              const float* __restrict__ W3a, const float* __restrict__ b3a,
              const float* __restrict__ W3b, const float* __restrict__ b3b,
              float* __restrict__ out)
{
    extern __shared__ char smem[];
    __nv_bfloat16* Xs = reinterpret_cast<__nv_bfloat16*>(smem + OFF_X);
    uint2* bp1 = reinterpret_cast<uint2*>(smem + OFF_BP1);
    uint2* bp2 = reinterpret_cast<uint2*>(smem + OFF_BP2);
    uint2* bp3 = reinterpret_cast<uint2*>(smem + OFF_BP3);
    uint4* ex  = reinterpret_cast<uint4*>(smem + OFF_EX);
    float* ps    = reinterpret_cast<float*>(smem + OFF_PS);
    float* xi    = reinterpret_cast<float*>(smem + OFF_XI);
    float* w3x   = reinterpret_cast<float*>(smem + OFF_W3X);
    float* b3a_s = reinterpret_cast<float*>(smem + OFF_B3A);
    float* w3b_s = reinterpret_cast<float*>(smem + OFF_W3B);
    float* b3b_s = reinterpret_cast<float*>(smem + OFF_B3B);

    const int tid   = threadIdx.x;
    const int node  = blockIdx.y;
    const int bbase = blockIdx.x * kBT;

    // ---------------- staging ----------------
    {   // X: mask col `node`, save fp32 x[:,node]
        const float* xg = x + (size_t)bbase * 64;
        for (int idx = tid; idx < kBT * 16; idx += kThreads) {
            const int row = idx >> 4, j = idx & 15;
            float4 v = *reinterpret_cast<const float4*>(xg + row * 64 + j * 4);
            if ((node >> 2) == j) {
                float* vv = reinterpret_cast<float*>(&v);
                xi[row] = vv[node & 3];
                vv[node & 3] = 0.0f;
            }
            *reinterpret_cast<uint2*>(Xs + row * kXS + j * 4) =
                make_uint2(bf2(v.x, v.y), bf2(v.z, v.w));
        }
    }
    // frag(s,n,t4) at uint2 idx ((s>>1)*NS + n)*8 + 2*t4 + (s&1); lane reads
    // uint4 (ksteps s,s+1) at uint4 idx sp*NS*4 + nt*32 + lane.
    {   // BP1: [W1a;W2a], n = h 0..127
        const float* w1 = W1a + (size_t)node * 4096;
        const float* w2 = W2a + (size_t)node * 4096;
        for (int t = tid; t < 512; t += kThreads) {
            const int n = t >> 2, s = t & 3;
            const float* src = (n < 64) ? (w1 + n * 64 + s * 16)
                                        : (w2 + (n - 64) * 64 + s * 16);
            uint2* dst = bp1 + (size_t)((s >> 1) * 128 + n) * 8 + (s & 1);
            #pragma unroll
            for (int t4 = 0; t4 < 4; t4++)
                dst[2 * t4] = make_uint2(bf2(src[2 * t4],     src[2 * t4 + 1]),
                                         bf2(src[2 * t4 + 8], src[2 * t4 + 9]));
        }
    }
    {   // BP2: br0 = W1b (k = H1 cols 0..63), br1 = W2b (cols 64..127)
        for (int t = tid; t < 256; t += kThreads) {
            const int br = t >> 7, rem = t & 127, m = rem >> 2, s = rem & 3;
            const float* src = (br ? W2b : W1b) + (size_t)node * 2048 + m * 64 + s * 16;
            uint2* dst = bp2 + (size_t)br * 512
                             + (size_t)((s >> 1) * 32 + m) * 8 + (s & 1);
            #pragma unroll
            for (int t4 = 0; t4 < 4; t4++)
                dst[2 * t4] = make_uint2(bf2(src[2 * t4],     src[2 * t4 + 1]),
                                         bf2(src[2 * t4 + 8], src[2 * t4 + 9]));
        }
    }
    {   // BP3: W3a[:,0:64], n = h
        const float* w3 = W3a + (size_t)node * 8192;
        for (int t = tid; t < 256; t += kThreads) {
            const int n = t >> 2, s = t & 3;
            const float* src = w3 + n * 128 + s * 16;
            uint2* dst = bp3 + (size_t)((s >> 1) * 64 + n) * 8 + (s & 1);
            #pragma unroll
            for (int t4 = 0; t4 < 4; t4++)
                dst[2 * t4] = make_uint2(bf2(src[2 * t4],     src[2 * t4 + 1]),
                                         bf2(src[2 * t4 + 8], src[2 * t4 + 9]));
        }
        if (tid < 64) {
            w3x[tid]   = w3[tid * 128 + 64 + node];
            b3a_s[tid] = b3a[node * 64 + tid];
            w3b_s[tid] = W3b[node * 64 + tid];
        }
        if (tid == 0) b3b_s[0] = b3b[node];
    }
    __syncthreads();

    // ---------------- branch-split warp-pair MLP ----------------
    const int wid = tid >> 5, lane = tid & 31;
    const int tg = lane >> 2, t4 = lane & 3;
    const int br = wid >> 2;          // branch handled by this warp
    const int rg = wid & 3;           // row group (shared with warp wid^4)
    const int r0 = rg * 32;

    const uint4* bp1q = reinterpret_cast<const uint4*>(bp1);
    const uint4* bp2q = reinterpret_cast<const uint4*>(bp2);
    const uint4* bp3q = reinterpret_cast<const uint4*>(bp3);

    // hoisted X A-fragments: 2 m16 tiles x 4 ksteps
    const int mat = lane >> 3, rin = lane & 7;
    const int arow = ((mat & 1) << 3) + rin;
    const int akb  = (mat >> 1) << 4;
    const uint32_t a_base = smem_u32(Xs) + (uint32_t)(r0 + arow) * 144 + akb;
    uint32_t XA[2][4][4];
    #pragma unroll
    for (int mt = 0; mt < 2; mt++)
        #pragma unroll
        for (int s = 0; s < 4; s++)
            ldmat4(XA[mt][s], a_base + mt * 16 * 144 + s * 32);

    // ---- L1, branch br only ----
    float accL1[2][8][4];
    #pragma unroll
    for (int mt = 0; mt < 2; mt++)
        #pragma unroll
        for (int nt = 0; nt < 8; nt++)
            #pragma unroll
            for (int i = 0; i < 4; i++) accL1[mt][nt][i] = 0.0f;
    #pragma unroll
    for (int sp = 0; sp < 2; sp++) {
        const uint4* bs = bp1q + sp * 512 + br * 256 + lane;
        #pragma unroll
        for (int nt = 0; nt < 8; nt++) {
            const uint4 q = bs[nt * 32];
            #pragma unroll
            for (int mt = 0; mt < 2; mt++) {
                mma16(accL1[mt][nt], XA[mt][2 * sp],     q.x, q.y);
                mma16(accL1[mt][nt], XA[mt][2 * sp + 1], q.z, q.w);
            }
        }
    }
    uint32_t A2[2][4][4];
    #pragma unroll
    for (int mt = 0; mt < 2; mt++)
        #pragma unroll
        for (int s = 0; s < 4; s++)
            pack2(A2[mt][s], accL1[mt][2 * s], accL1[mt][2 * s + 1]);

    // ---- L2, branch br only (32 outputs) ----
    float acc4[2][4][4];
    #pragma unroll
    for (int mt = 0; mt < 2; mt++)
        #pragma unroll
        for (int nt = 0; nt < 4; nt++)
            #pragma unroll
            for (int i = 0; i < 4; i++) acc4[mt][nt][i] = 0.0f;
    #pragma unroll
    for (int sp = 0; sp < 2; sp++) {
        const uint4* bs = bp2q + br * 256 + sp * 128 + lane;
        #pragma unroll
        for (int nt = 0; nt < 4; nt++) {
            const uint4 q = bs[nt * 32];
            #pragma unroll
            for (int mt = 0; mt < 2; mt++) {
                mma16(acc4[mt][nt], A2[mt][2 * sp],     q.x, q.y);
                mma16(acc4[mt][nt], A2[mt][2 * sp + 1], q.z, q.w);
            }
        }
    }
    // A3 local half: L3 ksteps {2br, 2br+1}
    uint32_t A3loc[2][2][4];
    #pragma unroll
    for (int mt = 0; mt < 2; mt++)
        #pragma unroll
        for (int s = 0; s < 2; s++)
            pack2(A3loc[mt][s], acc4[mt][2 * s], acc4[mt][2 * s + 1]);

    // ---- exchange A3 halves within the warp pair ----
    uint4* exw = ex + (size_t)wid * 128 + lane;
    #pragma unroll
    for (int mt = 0; mt < 2; mt++)
        #pragma unroll
        for (int s = 0; s < 2; s++)
            exw[(mt * 2 + s) * 32] =
                make_uint4(A3loc[mt][s][0], A3loc[mt][s][1],
                           A3loc[mt][s][2], A3loc[mt][s][3]);
    __syncthreads();
    uint32_t A3k[2][4][4];   // full A3 in kstep order 0..3
    {
        const uint4* exp_ = ex + (size_t)(wid ^ 4) * 128 + lane;
        #pragma unroll
        for (int mt = 0; mt < 2; mt++)
            #pragma unroll
            for (int s = 0; s < 2; s++) {
                const uint4 q = exp_[(mt * 2 + s) * 32];
                const int kloc = 2 * br + s;      // local ksteps
                const int koth = 2 * (1 - br) + s;
                A3k[mt][kloc][0] = A3loc[mt][s][0];
                A3k[mt][kloc][1] = A3loc[mt][s][1];
                A3k[mt][kloc][2] = A3loc[mt][s][2];
                A3k[mt][kloc][3] = A3loc[mt][s][3];
                A3k[mt][koth][0] = q.x; A3k[mt][koth][1] = q.y;
                A3k[mt][koth][2] = q.z; A3k[mt][koth][3] = q.w;
            }
    }

    // ---- L3: this warp covers n-tiles br*4 .. br*4+3 ----
    float acc[2][4][4];
    #pragma unroll
    for (int mt = 0; mt < 2; mt++)
        #pragma unroll
        for (int nt = 0; nt < 4; nt++)
            #pragma unroll
            for (int i = 0; i < 4; i++) acc[mt][nt][i] = 0.0f;
    #pragma unroll
    for (int sp = 0; sp < 2; sp++) {
        const uint4* bs = bp3q + sp * 256 + br * 128 + lane;
        #pragma unroll
        for (int nt = 0; nt < 4; nt++) {
            const uint4 q = bs[nt * 32];
            #pragma unroll
            for (int mt = 0; mt < 2; mt++) {
                mma16(acc[mt][nt], A3k[mt][2 * sp],     q.x, q.y);
                mma16(acc[mt][nt], A3k[mt][2 * sp + 1], q.z, q.w);
            }
        }
    }

    // ---- epilogue: partial over this warp's 32 h-columns ----
    float s0[2], s1[2];
    #pragma unroll
    for (int mt = 0; mt < 2; mt++) {
        const int ru = r0 + 16 * mt + tg;
        const float xu = xi[ru], xl = xi[ru + 8];
        float a = 0.f, b = 0.f;
        #pragma unroll
        for (int nt = 0; nt < 4; nt++) {
            const int c0 = br * 32 + 8 * nt + 2 * t4;
            const float wx0 = w3x[c0], wx1 = w3x[c0 + 1];
            const float ba0 = b3a_s[c0], ba1 = b3a_s[c0 + 1];
            const float wb0 = w3b_s[c0], wb1 = w3b_s[c0 + 1];
            a += fmaxf(acc[mt][nt][0] + xu * wx0 + ba0, 0.f) * wb0
               + fmaxf(acc[mt][nt][1] + xu * wx1 + ba1, 0.f) * wb1;
            b += fmaxf(acc[mt][nt][2] + xl * wx0 + ba0, 0.f) * wb0
               + fmaxf(acc[mt][nt][3] + xl * wx1 + ba1, 0.f) * wb1;
        }
        a += __shfl_xor_sync(0xffffffff, a, 1);
        a += __shfl_xor_sync(0xffffffff, a, 2);
        b += __shfl_xor_sync(0xffffffff, b, 1);
        b += __shfl_xor_sync(0xffffffff, b, 2);
        s0[mt] = a; s1[mt] = b;
    }
    // combine across the warp pair via smem
    if (br == 1 && t4 == 0) {
        #pragma unroll
        for (int mt = 0; mt < 2; mt++) {
            ps[r0 + 16 * mt + tg]     = s0[mt];
            ps[r0 + 16 * mt + tg + 8] = s1[mt];
        }
    }
    __syncthreads();
    if (br == 0 && t4 == 0) {
        const float bb = b3b_s[0];
        #pragma unroll
        for (int mt = 0; mt < 2; mt++) {
            const int ru = r0 + 16 * mt + tg;
            out[(size_t)(bbase + ru) * 64 + node] =
                fmaxf(s0[mt] + ps[ru] + bb, 0.f);
            out[(size_t)(bbase + ru + 8) * 64 + node] =
                fmaxf(s1[mt] + ps[ru + 8] + bb, 0.f);
        }
    }
}

extern "C" void kernel_launch(void* const* d_in, const int* in_sizes, int n_in,
                              void* d_out, int out_size)
{
    (void)in_sizes; (void)n_in; (void)out_size;
    const float* x   = (const float*)d_in[0];
    const float* W1a = (const float*)d_in[1];
    const float* W1b = (const float*)d_in[2];
    const float* W2a = (const float*)d_in[3];
    const float* W2b = (const float*)d_in[4];
    const float* W3a = (const float*)d_in[5];
    const float* b3a = (const float*)d_in[6];
    const float* W3b = (const float*)d_in[7];
    const float* b3b = (const float*)d_in[8];
    float* out = (float*)d_out;

    cudaFuncSetAttribute(ctp_r7_kernel,
                         cudaFuncAttributeMaxDynamicSharedMemorySize,
                         (int)SMEM_BYTES);
    dim3 grid(kB / kBT, 64);   // 128 batch tiles x 64 nodes
    ctp_r7_kernel<<<grid, kThreads, SMEM_BYTES>>>(
        x, W1a, W1b, W2a, W2b, W3a, b3a, W3b, b3b, out);
}

// round 8
// speedup vs baseline: 3.0289x; 3.0289x over previous
#include <cuda_runtime.h>
#include <cuda_bf16.h>
#include <cstdint>

// CausalTrajectoryPrediction: fused 3-GEMM MLP, mma.sync m16n8k16 bf16,
// register-chained (R5 compute path — best known). R8: the fragment-layout
// weight repack (scattered, bank-conflicted STS) is hoisted into a tiny
// per-node pre-kernel writing a __device__ global buffer; the main kernel
// stages weights with a coalesced conflict-free bulk copy (L2-resident).

namespace {
constexpr int kB       = 16384;
constexpr int kBT      = 256;
constexpr int kThreads = 256;
constexpr int kXS      = 72;     // X row stride in bf16 elems (144 B)

// per-node repacked weights: uint2 units
//   BP1 [0,2048): [W1a;W2a] frags   (16 KB)
//   BP2 [2048,3072): W1b|W2b frags  ( 8 KB)
//   BP3 [3072,4096): W3a[:,0:64]    ( 8 KB)
constexpr int kBPN = 4096;       // uint2 per node

constexpr uint32_t OFF_X   = 0;          // bf16 [256][72] = 36864
constexpr uint32_t OFF_BP  = 36864;      // 32 KB (BP1|BP2|BP3)
constexpr uint32_t OFF_XI  = 69632;      // float [256]
constexpr uint32_t OFF_W3X = 70656;      // float [64]
constexpr uint32_t OFF_B3A = 70912;      // float [64]
constexpr uint32_t OFF_W3B = 71168;      // float [64]
constexpr uint32_t OFF_B3B = 71424;      // float
constexpr uint32_t SMEM_BYTES = 71440;
} // namespace

__device__ uint2 g_bp[64 * kBPN];        // 2 MB repacked weights
__device__ float g_vec[64 * 256];        // per node: w3x[64] b3a[64] w3b[64] b3b

__device__ __forceinline__ uint32_t smem_u32(const void* p) {
    uint32_t a;
    asm("{ .reg .u64 t; cvta.to.shared.u64 t, %1; cvt.u32.u64 %0, t; }"
        : "=r"(a) : "l"(p));
    return a;
}
__device__ __forceinline__ uint32_t bf2(float a, float b) {
    __nv_bfloat162 h = __floats2bfloat162_rn(a, b);
    return *reinterpret_cast<uint32_t*>(&h);
}
__device__ __forceinline__ void ldmat4(uint32_t r[4], uint32_t saddr) {
    asm volatile("ldmatrix.sync.aligned.m8n8.x4.shared.b16 {%0,%1,%2,%3}, [%4];"
                 : "=r"(r[0]), "=r"(r[1]), "=r"(r[2]), "=r"(r[3]) : "r"(saddr));
}
__device__ __forceinline__ void mma16(float d[4], const uint32_t a[4], uint2 b) {
    asm volatile(
        "mma.sync.aligned.m16n8k16.row.col.f32.bf16.bf16.f32 "
        "{%0,%1,%2,%3}, {%4,%5,%6,%7}, {%8,%9}, {%0,%1,%2,%3};"
        : "+f"(d[0]), "+f"(d[1]), "+f"(d[2]), "+f"(d[3])
        : "r"(a[0]), "r"(a[1]), "r"(a[2]), "r"(a[3]), "r"(b.x), "r"(b.y));
}
__device__ __forceinline__ void pack2(uint32_t a[4], const float c0[4],
                                      const float c1[4]) {
    a[0] = bf2(fmaxf(c0[0], 0.f), fmaxf(c0[1], 0.f));
    a[1] = bf2(fmaxf(c0[2], 0.f), fmaxf(c0[3], 0.f));
    a[2] = bf2(fmaxf(c1[0], 0.f), fmaxf(c1[1], 0.f));
    a[3] = bf2(fmaxf(c1[2], 0.f), fmaxf(c1[3], 0.f));
}

// ---------------- repack kernel: one block per node ----------------
__global__ void __launch_bounds__(256)
ctp_repack_kernel(const float* __restrict__ W1a, const float* __restrict__ W1b,
                  const float* __restrict__ W2a, const float* __restrict__ W2b,
                  const float* __restrict__ W3a, const float* __restrict__ b3a,
                  const float* __restrict__ W3b, const float* __restrict__ b3b)
{
    const int node = blockIdx.x;
    const int tid  = threadIdx.x;
    uint2* bp1 = g_bp + (size_t)node * kBPN;
    uint2* bp2 = bp1 + 2048;
    uint2* bp3 = bp1 + 3072;

    {   // BP1: [W1a;W2a] as B[n=h 0..127][k], frag-paired
        const float* w1 = W1a + (size_t)node * 4096;
        const float* w2 = W2a + (size_t)node * 4096;
        for (int t = tid; t < 512; t += 256) {
            const int n = t >> 2, s = t & 3;
            const float* src = (n < 64) ? (w1 + n * 64 + s * 16)
                                        : (w2 + (n - 64) * 64 + s * 16);
            uint2* dst = bp1 + (size_t)(s * 128 + n) * 4;
            #pragma unroll
            for (int t4 = 0; t4 < 4; t4++)
                dst[t4] = make_uint2(bf2(src[2 * t4],     src[2 * t4 + 1]),
                                     bf2(src[2 * t4 + 8], src[2 * t4 + 9]));
        }
    }
    {   // BP2: br0 = W1b (k = H1 cols 0..63), br1 = W2b (cols 64..127)
        for (int t = tid; t < 256; t += 256) {
            const int br = t >> 7, rem = t & 127, m = rem >> 2, s = rem & 3;
            const float* src = (br ? W2b : W1b) + (size_t)node * 2048 + m * 64 + s * 16;
            uint2* dst = bp2 + (size_t)((br * 4 + s) * 32 + m) * 4;
            #pragma unroll
            for (int t4 = 0; t4 < 4; t4++)
                dst[t4] = make_uint2(bf2(src[2 * t4],     src[2 * t4 + 1]),
                                     bf2(src[2 * t4 + 8], src[2 * t4 + 9]));
        }
    }
    {   // BP3: W3a[:,0:64] as B[n=h][k=c]
        const float* w3 = W3a + (size_t)node * 8192;
        for (int t = tid; t < 256; t += 256) {
            const int n = t >> 2, s = t & 3;
            const float* src = w3 + n * 128 + s * 16;
            uint2* dst = bp3 + (size_t)(s * 64 + n) * 4;
            #pragma unroll
            for (int t4 = 0; t4 < 4; t4++)
                dst[t4] = make_uint2(bf2(src[2 * t4],     src[2 * t4 + 1]),
                                     bf2(src[2 * t4 + 8], src[2 * t4 + 9]));
        }
        float* vec = g_vec + node * 256;
        if (tid < 64) {
            vec[tid]       = w3[tid * 128 + 64 + node];   // w3x
            vec[64 + tid]  = b3a[node * 64 + tid];
            vec[128 + tid] = W3b[node * 64 + tid];
        }
        if (tid == 0) vec[192] = b3b[node];
    }
}

// ---------------- main kernel ----------------
__global__ void __launch_bounds__(kThreads, 2)
ctp_r8_kernel(const float* __restrict__ x, float* __restrict__ out)
{
    extern __shared__ char smem[];
    __nv_bfloat16* Xs = reinterpret_cast<__nv_bfloat16*>(smem + OFF_X);
    uint2* bp1 = reinterpret_cast<uint2*>(smem + OFF_BP);
    uint2* bp2 = bp1 + 2048;
    uint2* bp3 = bp1 + 3072;
    float* xi    = reinterpret_cast<float*>(smem + OFF_XI);
    float* w3x   = reinterpret_cast<float*>(smem + OFF_W3X);
    float* b3a_s = reinterpret_cast<float*>(smem + OFF_B3A);
    float* w3b_s = reinterpret_cast<float*>(smem + OFF_W3B);
    float* b3b_s = reinterpret_cast<float*>(smem + OFF_B3B);

    const int tid   = threadIdx.x;
    const int node  = blockIdx.y;
    const int bbase = blockIdx.x * kBT;

    // ---- staging: coalesced bulk copy of repacked weights ----
    {
        const uint4* src = reinterpret_cast<const uint4*>(g_bp + (size_t)node * kBPN);
        uint4* dst = reinterpret_cast<uint4*>(bp1);
        #pragma unroll
        for (int t = tid; t < 2048; t += kThreads) dst[t] = src[t];
        const float* vec = g_vec + node * 256;
        if (tid < 64) {
            w3x[tid]   = vec[tid];
            b3a_s[tid] = vec[64 + tid];
            w3b_s[tid] = vec[128 + tid];
        }
        if (tid == 0) b3b_s[0] = vec[192];
    }
    // ---- X: mask col `node`, save fp32 x[:,node] ----
    {
        const float* xg = x + (size_t)bbase * 64;
        for (int idx = tid; idx < kBT * 16; idx += kThreads) {
            const int row = idx >> 4, j = idx & 15;
            float4 v = *reinterpret_cast<const float4*>(xg + row * 64 + j * 4);
            if ((node >> 2) == j) {
                float* vv = reinterpret_cast<float*>(&v);
                xi[row] = vv[node & 3];
                vv[node & 3] = 0.0f;
            }
            *reinterpret_cast<uint2*>(Xs + row * kXS + j * 4) =
                make_uint2(bf2(v.x, v.y), bf2(v.z, v.w));
        }
    }
    __syncthreads();

    // ---------------- per-warp register-chained MLP (R5 path) ----------------
    const int wid = tid >> 5, lane = tid & 31;
    const int tg = lane >> 2, t4 = lane & 3;
    const int r0 = wid * 32;

    const int mat = lane >> 3, rin = lane & 7;
    const int arow = ((mat & 1) << 3) + rin;
    const int akb  = (mat >> 1) << 4;
    const uint32_t a_base0 = smem_u32(Xs) + (uint32_t)(r0 + arow) * 144 + akb;

    float acc[2][8][4];
    float acc4[2][4][4];
    uint32_t A2[2][4][4];
    uint32_t A3[2][4][4];

    // L1 half + L2 branch, br = 0 then 1 (A2 reused)
    #pragma unroll
    for (int br = 0; br < 2; br++) {
        #pragma unroll
        for (int mt = 0; mt < 2; mt++)
            #pragma unroll
            for (int nt = 0; nt < 8; nt++)
                #pragma unroll
                for (int i = 0; i < 4; i++) acc[mt][nt][i] = 0.0f;
        #pragma unroll
        for (int s = 0; s < 4; s++) {
            uint32_t a0[4], a1[4];
            ldmat4(a0, a_base0 + s * 32);
            ldmat4(a1, a_base0 + s * 32 + 16 * 144);
            const uint2* bs = bp1 + (size_t)s * 512 + br * 256 + lane;
            #pragma unroll
            for (int nt = 0; nt < 8; nt++) {
                const uint2 bv = bs[nt * 32];
                mma16(acc[0][nt], a0, bv);
                mma16(acc[1][nt], a1, bv);
            }
        }
        #pragma unroll
        for (int mt = 0; mt < 2; mt++)
            #pragma unroll
            for (int s = 0; s < 4; s++)
                pack2(A2[mt][s], acc[mt][2 * s], acc[mt][2 * s + 1]);

        #pragma unroll
        for (int mt = 0; mt < 2; mt++)
            #pragma unroll
            for (int nt = 0; nt < 4; nt++)
                #pragma unroll
                for (int i = 0; i < 4; i++) acc4[mt][nt][i] = 0.0f;
        #pragma unroll
        for (int s = 0; s < 4; s++) {
            const uint2* bs = bp2 + (size_t)(br * 4 + s) * 128 + lane;
            #pragma unroll
            for (int nt = 0; nt < 4; nt++) {
                const uint2 bv = bs[nt * 32];
                mma16(acc4[0][nt], A2[0][s], bv);
                mma16(acc4[1][nt], A2[1][s], bv);
            }
        }
        #pragma unroll
        for (int mt = 0; mt < 2; mt++)
            #pragma unroll
            for (int s = 0; s < 2; s++)
                pack2(A3[mt][2 * br + s], acc4[mt][2 * s], acc4[mt][2 * s + 1]);
    }

    // L3 (K=64, 64 outputs)
    #pragma unroll
    for (int mt = 0; mt < 2; mt++)
        #pragma unroll
        for (int nt = 0; nt < 8; nt++)
            #pragma unroll
            for (int i = 0; i < 4; i++) acc[mt][nt][i] = 0.0f;
    #pragma unroll
    for (int s = 0; s < 4; s++) {
        const uint2* bs = bp3 + (size_t)s * 256 + lane;
        #pragma unroll
        for (int nt = 0; nt < 8; nt++) {
            const uint2 bv = bs[nt * 32];
            mma16(acc[0][nt], A3[0][s], bv);
            mma16(acc[1][nt], A3[1][s], bv);
        }
    }

    // epilogue (fp32)
    float s2[2][2] = {{0.f, 0.f}, {0.f, 0.f}};
    #pragma unroll
    for (int mt = 0; mt < 2; mt++) {
        const int ru = r0 + 16 * mt + tg;
        const float xu = xi[ru], xl = xi[ru + 8];
        #pragma unroll
        for (int nt = 0; nt < 8; nt++) {
            const int c0 = 8 * nt + 2 * t4;
            const float wx0 = w3x[c0], wx1 = w3x[c0 + 1];
            const float ba0 = b3a_s[c0], ba1 = b3a_s[c0 + 1];
            const float wb0 = w3b_s[c0], wb1 = w3b_s[c0 + 1];
            s2[mt][0] += fmaxf(acc[mt][nt][0] + xu * wx0 + ba0, 0.f) * wb0
                       + fmaxf(acc[mt][nt][1] + xu * wx1 + ba1, 0.f) * wb1;
            s2[mt][1] += fmaxf(acc[mt][nt][2] + xl * wx0 + ba0, 0.f) * wb0
                       + fmaxf(acc[mt][nt][3] + xl * wx1 + ba1, 0.f) * wb1;
        }
    }
    const float bb = b3b_s[0];
    #pragma unroll
    for (int mt = 0; mt < 2; mt++)
        #pragma unroll
        for (int half = 0; half < 2; half++) {
            float v = s2[mt][half];
            v += __shfl_xor_sync(0xffffffff, v, 1);
            v += __shfl_xor_sync(0xffffffff, v, 2);
            if (t4 == 0) {
                const int ru = r0 + 16 * mt + tg + 8 * half;
                out[(size_t)(bbase + ru) * 64 + node] = fmaxf(v + bb, 0.f);
            }
        }
}

extern "C" void kernel_launch(void* const* d_in, const int* in_sizes, int n_in,
                              void* d_out, int out_size)
{
    (void)in_sizes; (void)n_in; (void)out_size;
    const float* x   = (const float*)d_in[0];
    const float* W1a = (const float*)d_in[1];
    const float* W1b = (const float*)d_in[2];
    const float* W2a = (const float*)d_in[3];
    const float* W2b = (const float*)d_in[4];
    const float* W3a = (const float*)d_in[5];
    const float* b3a = (const float*)d_in[6];
    const float* W3b = (const float*)d_in[7];
    const float* b3b = (const float*)d_in[8];
    float* out = (float*)d_out;

    ctp_repack_kernel<<<64, 256>>>(W1a, W1b, W2a, W2b, W3a, b3a, W3b, b3b);

    cudaFuncSetAttribute(ctp_r8_kernel,
                         cudaFuncAttributeMaxDynamicSharedMemorySize,
                         (int)SMEM_BYTES);
    dim3 grid(kB / kBT, 64);   // 64 batch tiles x 64 nodes
    ctp_r8_kernel<<<grid, kThreads, SMEM_BYTES>>>(x, out);
}